// round 11
// baseline (speedup 1.0000x reference)
#include <cuda_runtime.h>
#include <stdint.h>

// Problem constants: B=16, L=4096, H=768 (fp32)
#define B_ 16
#define L_ 4096
#define H_ 768
#define H4 (H_ / 4)            // 192 float4 lanes per row
#define TOK_PER_BLK 16         // tokens per block tile
#define SROWS 6                // rows per pipeline stage (18 KB)
#define NSTAGES 3              // pipeline depth (54 KB smem)
#define NWARPS (H4 / 32)       // 6
#define BLOCKS_PER_BATCH (L_ / TOK_PER_BLK)  // 256

__device__ __forceinline__ uint32_t smem_u32(const void* p) {
    uint32_t a;
    asm("{ .reg .u64 tmp; cvta.to.shared.u64 tmp, %1; cvt.u32.u64 %0, tmp; }"
        : "=r"(a) : "l"(p));
    return a;
}

__device__ __forceinline__ void mbar_init(uint32_t mbar, uint32_t cnt) {
    asm volatile("mbarrier.init.shared.b64 [%0], %1;" :: "r"(mbar), "r"(cnt) : "memory");
}
__device__ __forceinline__ void mbar_expect_tx(uint32_t mbar, uint32_t bytes) {
    asm volatile("mbarrier.arrive.expect_tx.shared.b64 _, [%0], %1;"
                 :: "r"(mbar), "r"(bytes) : "memory");
}
__device__ __forceinline__ void mbar_arrive(uint32_t mbar) {
    asm volatile("mbarrier.arrive.shared.b64 _, [%0];" :: "r"(mbar) : "memory");
}
__device__ __forceinline__ void mbar_wait(uint32_t mbar, uint32_t parity) {
    uint32_t done;
    asm volatile(
        "{\n\t.reg .pred p;\n\t"
        "mbarrier.try_wait.parity.acquire.cta.shared::cta.b64 p, [%1], %2;\n\t"
        "selp.b32 %0, 1, 0, p;\n\t}"
        : "=r"(done) : "r"(mbar), "r"(parity) : "memory");
    if (!done) {
        asm volatile(
            "{\n\t.reg .pred P1;\n\t"
            "WL_%=:\n\t"
            "mbarrier.try_wait.parity.acquire.cta.shared::cta.b64 P1, [%0], %1, 0x989680;\n\t"
            "@P1 bra.uni WD_%=;\n\t"
            "bra.uni WL_%=;\n\t"
            "WD_%=:\n\t}"
            :: "r"(mbar), "r"(parity) : "memory");
    }
}
__device__ __forceinline__ void bulk_copy_g2s(uint32_t dst_smem, const void* src,
                                              uint32_t bytes, uint32_t mbar) {
    asm volatile(
        "cp.async.bulk.shared::cta.global.mbarrier::complete_tx::bytes "
        "[%0], [%1], %2, [%3];"
        :: "r"(dst_smem), "l"(src), "r"(bytes), "r"(mbar) : "memory");
}

__global__ __launch_bounds__(H4)
void token_segment_sum_kernel(const float* __restrict__ x,
                              const int*   __restrict__ seg,
                              float*       __restrict__ out)
{
    __shared__ alignas(16) float4 buf[NSTAGES][SROWS * H4];   // 54 KB
    __shared__ alignas(8) uint64_t mb_full[NSTAGES];
    __shared__ alignas(8) uint64_t mb_empty[NSTAGES];
    __shared__ int bnd[TOK_PER_BLK + 1];

    const int b    = blockIdx.x / BLOCKS_PER_BATCH;
    const int tile = blockIdx.x % BLOCKS_PER_BATCH;
    const int j0   = tile * TOK_PER_BLK;

    const int* __restrict__ segb = seg + b * L_;
    const int t = threadIdx.x;   // 0..191 (float4 lane)

    if (t < NSTAGES) {
        mbar_init(smem_u32(&mb_full[t]), 1);        // completed by TMA tx bytes
        mbar_init(smem_u32(&mb_empty[t]), NWARPS);  // one arrive per warp
    }
    if (t <= TOK_PER_BLK) {
        // lower_bound: first index i with segb[i] >= (j0 + t)
        const int target = j0 + t;
        int lo = 0, hi = L_;
        #pragma unroll 1
        while (lo < hi) {
            int mid = (lo + hi) >> 1;
            if (segb[mid] < target) lo = mid + 1; else hi = mid;
        }
        bnd[t] = lo;
    }
    __syncthreads();

    const float4* __restrict__ xb =
        reinterpret_cast<const float4*>(x + (size_t)b * L_ * H_);
    float4* __restrict__ ob =
        reinterpret_cast<float4*>(out + (size_t)b * L_ * H_);

    const int s0 = bnd[0];
    const int s1 = bnd[TOK_PER_BLK];
    const int nrows = s1 - s0;
    const int nchunks = (nrows + SROWS - 1) / SROWS;

    int j = 0;

    // tokens empty at the very start (bnd[j+1] == s0) -> zero rows
    #pragma unroll 1
    while (j < TOK_PER_BLK && bnd[j + 1] == s0) {
        ob[(size_t)(j0 + j) * H4 + t] = make_float4(0.f, 0.f, 0.f, 0.f);
        j++;
    }
    if (nchunks == 0) return;

    // producer: prime the pipeline (up to NSTAGES chunks in flight)
    if (t == 0) {
        const int prime = min(NSTAGES, nchunks);
        #pragma unroll 1
        for (int c = 0; c < prime; c++) {
            const int rbase = s0 + c * SROWS;
            const uint32_t bytes = (uint32_t)min(SROWS, s1 - rbase) * (H_ * 4);
            const uint32_t fm = smem_u32(&mb_full[c]);
            mbar_expect_tx(fm, bytes);
            bulk_copy_g2s(smem_u32(&buf[c][0]), &xb[(size_t)rbase * H4], bytes, fm);
        }
    }

    // register-cached next boundary: common row path has NO shared-mem read
    int nb = (j < TOK_PER_BLK) ? bnd[j + 1] : -1;
    float4 acc = make_float4(0.f, 0.f, 0.f, 0.f);

    const int lane = t & 31;

    #pragma unroll 1
    for (int c = 0; c < nchunks; c++) {
        const int s  = c % NSTAGES;
        const uint32_t ph = (uint32_t)((c / NSTAGES) & 1);
        const int rbase = s0 + c * SROWS;
        const int n = min(SROWS, s1 - rbase);

        mbar_wait(smem_u32(&mb_full[s]), ph);

        #pragma unroll
        for (int i = 0; i < SROWS; i++) {
            if (i < n) {
                float4 v = buf[s][i * H4 + t];
                acc.x += v.x; acc.y += v.y;
                acc.z += v.z; acc.w += v.w;
                const int pos1 = rbase + i + 1;
                if (pos1 == nb) {          // rare: token(s) end here
                    do {
                        ob[(size_t)(j0 + j) * H4 + t] = acc;
                        acc = make_float4(0.f, 0.f, 0.f, 0.f);
                        j++;
                        nb = (j < TOK_PER_BLK) ? bnd[j + 1] : -1;
                    } while (nb == pos1);  // equal bounds = empty tokens
                }
            }
        }

        // release the stage — ONE arrive per warp (mb_empty count = NWARPS)
        __syncwarp();
        if (lane == 0) mbar_arrive(smem_u32(&mb_empty[s]));

        if (t == 0) {
            const int cn = c + NSTAGES;
            if (cn < nchunks) {
                mbar_wait(smem_u32(&mb_empty[s]), ph);
                const int rb2 = s0 + cn * SROWS;
                const uint32_t bytes = (uint32_t)min(SROWS, s1 - rb2) * (H_ * 4);
                const uint32_t fm = smem_u32(&mb_full[s]);
                mbar_expect_tx(fm, bytes);
                bulk_copy_g2s(smem_u32(&buf[s][0]), &xb[(size_t)rb2 * H4], bytes, fm);
            }
        }
    }
}

extern "C" void kernel_launch(void* const* d_in, const int* in_sizes, int n_in,
                              void* d_out, int out_size)
{
    const float* x   = (const float*)d_in[0];   // sequence_output  [B, L, H] f32
    const int*   seg = (const int*)  d_in[1];   // wordpiece_to_token [B, L] i32
    float*       out = (float*)d_out;           // [B, L, H] f32

    dim3 grid(B_ * BLOCKS_PER_BATCH);           // 4096 blocks
    dim3 block(H4);                             // 192 threads
    token_segment_sum_kernel<<<grid, block>>>(x, seg, out);
}

// round 12
// speedup vs baseline: 1.0583x; 1.0583x over previous
#include <cuda_runtime.h>
#include <stdint.h>

// Problem constants: B=16, L=4096, H=768 (fp32)
#define B_ 16
#define L_ 4096
#define H_ 768
#define H4 (H_ / 4)            // 192 float4 lanes per row
#define TOK_PER_BLK 16         // tokens per block tile
#define SROWS 4                // rows per pipeline stage (12 KB)
#define NSTAGES 3              // pipeline depth (36 KB smem)
#define NCWARPS 6              // consumer warps (192 lanes)
#define NTHREADS 224           // 6 consumer warps + 1 producer warp
#define BLOCKS_PER_BATCH (L_ / TOK_PER_BLK)  // 256

__device__ __forceinline__ uint32_t smem_u32(const void* p) {
    uint32_t a;
    asm("{ .reg .u64 tmp; cvta.to.shared.u64 tmp, %1; cvt.u32.u64 %0, tmp; }"
        : "=r"(a) : "l"(p));
    return a;
}
__device__ __forceinline__ void mbar_init(uint32_t mbar, uint32_t cnt) {
    asm volatile("mbarrier.init.shared.b64 [%0], %1;" :: "r"(mbar), "r"(cnt) : "memory");
}
__device__ __forceinline__ void mbar_expect_tx(uint32_t mbar, uint32_t bytes) {
    asm volatile("mbarrier.arrive.expect_tx.shared.b64 _, [%0], %1;"
                 :: "r"(mbar), "r"(bytes) : "memory");
}
__device__ __forceinline__ void mbar_arrive(uint32_t mbar) {
    asm volatile("mbarrier.arrive.shared.b64 _, [%0];" :: "r"(mbar) : "memory");
}
__device__ __forceinline__ void mbar_wait(uint32_t mbar, uint32_t parity) {
    uint32_t done;
    asm volatile(
        "{\n\t.reg .pred p;\n\t"
        "mbarrier.try_wait.parity.acquire.cta.shared::cta.b64 p, [%1], %2;\n\t"
        "selp.b32 %0, 1, 0, p;\n\t}"
        : "=r"(done) : "r"(mbar), "r"(parity) : "memory");
    if (!done) {
        asm volatile(
            "{\n\t.reg .pred P1;\n\t"
            "WL_%=:\n\t"
            "mbarrier.try_wait.parity.acquire.cta.shared::cta.b64 P1, [%0], %1, 0x989680;\n\t"
            "@P1 bra.uni WD_%=;\n\t"
            "bra.uni WL_%=;\n\t"
            "WD_%=:\n\t}"
            :: "r"(mbar), "r"(parity) : "memory");
    }
}
__device__ __forceinline__ void bulk_copy_g2s(uint32_t dst_smem, const void* src,
                                              uint32_t bytes, uint32_t mbar) {
    asm volatile(
        "cp.async.bulk.shared::cta.global.mbarrier::complete_tx::bytes "
        "[%0], [%1], %2, [%3];"
        :: "r"(dst_smem), "l"(src), "r"(bytes), "r"(mbar) : "memory");
}

__global__ __launch_bounds__(NTHREADS)
void token_segment_sum_kernel(const float* __restrict__ x,
                              const int*   __restrict__ seg,
                              float*       __restrict__ out)
{
    __shared__ alignas(16) float4 buf[NSTAGES][SROWS * H4];   // 36 KB
    __shared__ alignas(8) uint64_t mb_full[NSTAGES];
    __shared__ alignas(8) uint64_t mb_empty[NSTAGES];
    __shared__ int bnd[TOK_PER_BLK + 1];

    const int b    = blockIdx.x / BLOCKS_PER_BATCH;
    const int tile = blockIdx.x % BLOCKS_PER_BATCH;
    const int j0   = tile * TOK_PER_BLK;

    const int* __restrict__ segb = seg + b * L_;
    const int t   = threadIdx.x;        // 0..223
    const int wid = t >> 5;             // 0..6 (warp 6 = producer)

    if (t < NSTAGES) {
        mbar_init(smem_u32(&mb_full[t]), 1);         // completed by TMA tx bytes
        mbar_init(smem_u32(&mb_empty[t]), NCWARPS);  // one arrive per consumer warp
    }
    if (t <= TOK_PER_BLK) {
        // lower_bound: first index i with segb[i] >= (j0 + t)
        const int target = j0 + t;
        int lo = 0, hi = L_;
        #pragma unroll 1
        while (lo < hi) {
            int mid = (lo + hi) >> 1;
            if (segb[mid] < target) lo = mid + 1; else hi = mid;
        }
        bnd[t] = lo;
    }
    __syncthreads();

    const float4* __restrict__ xb =
        reinterpret_cast<const float4*>(x + (size_t)b * L_ * H_);

    const int s0 = bnd[0];
    const int s1 = bnd[TOK_PER_BLK];
    const int nchunks = (s1 - s0 + SROWS - 1) / SROWS;

    if (wid == NCWARPS) {
        // ---------------- PRODUCER WARP (runs ahead autonomously) ----------
        if ((t & 31) == 0) {
            #pragma unroll 1
            for (int c = 0; c < nchunks; c++) {
                const int s = c % NSTAGES;
                const int lap = c / NSTAGES;
                if (lap > 0)
                    mbar_wait(smem_u32(&mb_empty[s]), (uint32_t)((lap - 1) & 1));
                const int rbase = s0 + c * SROWS;
                const uint32_t bytes =
                    (uint32_t)min(SROWS, s1 - rbase) * (H_ * 4);
                const uint32_t fm = smem_u32(&mb_full[s]);
                mbar_expect_tx(fm, bytes);
                bulk_copy_g2s(smem_u32(&buf[s][0]),
                              &xb[(size_t)rbase * H4], bytes, fm);
            }
        }
        return;
    }

    // ---------------- CONSUMER WARPS (192 lanes) ---------------------------
    float4* __restrict__ ob =
        reinterpret_cast<float4*>(out + (size_t)b * L_ * H_);

    int j = 0;

    // tokens empty at the very start (bnd[j+1] == s0) -> zero rows
    #pragma unroll 1
    while (j < TOK_PER_BLK && bnd[j + 1] == s0) {
        ob[(size_t)(j0 + j) * H4 + t] = make_float4(0.f, 0.f, 0.f, 0.f);
        j++;
    }
    if (nchunks == 0) return;

    // register-cached next boundary: common row path has NO shared-mem read
    int nb = (j < TOK_PER_BLK) ? bnd[j + 1] : -1;
    float4 acc = make_float4(0.f, 0.f, 0.f, 0.f);
    const int lane = t & 31;

    #pragma unroll 1
    for (int c = 0; c < nchunks; c++) {
        const int s  = c % NSTAGES;
        const uint32_t ph = (uint32_t)((c / NSTAGES) & 1);
        const int rbase = s0 + c * SROWS;
        const int n = min(SROWS, s1 - rbase);

        mbar_wait(smem_u32(&mb_full[s]), ph);

        #pragma unroll
        for (int i = 0; i < SROWS; i++) {
            if (i < n) {
                float4 v = buf[s][i * H4 + t];
                acc.x += v.x; acc.y += v.y;
                acc.z += v.z; acc.w += v.w;
                const int pos1 = rbase + i + 1;
                if (pos1 == nb) {          // rare: token(s) end here
                    do {
                        ob[(size_t)(j0 + j) * H4 + t] = acc;
                        acc = make_float4(0.f, 0.f, 0.f, 0.f);
                        j++;
                        nb = (j < TOK_PER_BLK) ? bnd[j + 1] : -1;
                    } while (nb == pos1);  // equal bounds = empty tokens
                }
            }
        }

        // release the stage — ONE arrive per consumer warp
        __syncwarp();
        if (lane == 0) mbar_arrive(smem_u32(&mb_empty[s]));
    }
}

extern "C" void kernel_launch(void* const* d_in, const int* in_sizes, int n_in,
                              void* d_out, int out_size)
{
    const float* x   = (const float*)d_in[0];   // sequence_output  [B, L, H] f32
    const int*   seg = (const int*)  d_in[1];   // wordpiece_to_token [B, L] i32
    float*       out = (float*)d_out;           // [B, L, H] f32

    dim3 grid(B_ * BLOCKS_PER_BATCH);           // 4096 blocks
    dim3 block(NTHREADS);                       // 224 threads (6+1 warps)
    token_segment_sum_kernel<<<grid, block>>>(x, seg, out);
}